// round 1
// baseline (speedup 1.0000x reference)
#include <cuda_runtime.h>
#include <cuda_bf16.h>

// Problem constants (verified against reference_code):
//   x:          (1, 2048, 4096) fp32   -> T=2048 tokens, K=4096
//   values:     (1024, 64, 64)  fp32   -> N_BLOCKS=1024, TM=TK=64
//   bias:       (4096,)         fp32   -> M=4096
//   block_rows: (1024,) int32 in [0,64)
//   block_cols: (1024,) int32 in [0,64)
//   out:        (1, 2048, 4096) fp32
#define KDIM   4096
#define MDIM   4096
#define NBLK   1024
#define BT     64     // token tile per CTA
#define BM     64     // M rows per CTA (one row-block)

// Scratch for transposed values: [n][k][m] (16 MB). __device__ global is the
// allowed scratch mechanism (no allocations permitted).
__device__ float g_vT[NBLK * 64 * 64];

// ---------------------------------------------------------------------------
// Pre-pass: transpose each 64x64 value block from [m][k] to [k][m].
// ---------------------------------------------------------------------------
__global__ void __launch_bounds__(256) transpose_values_kernel(
    const float* __restrict__ values, int n_blocks)
{
    __shared__ float tile[64][65];
    int n = blockIdx.x;
    if (n >= n_blocks) return;
    const float* src = values + (size_t)n * 64 * 64;
    float* dst = g_vT + (size_t)n * 64 * 64;

    #pragma unroll
    for (int i = threadIdx.x; i < 64 * 64; i += 256) {
        int m = i >> 6, k = i & 63;
        tile[m][k] = src[i];            // coalesced global read
    }
    __syncthreads();
    #pragma unroll
    for (int i = threadIdx.x; i < 64 * 64; i += 256) {
        int k = i >> 6, m = i & 63;
        dst[i] = tile[m][k];            // coalesced global write, pad avoids conflicts
    }
}

__device__ __forceinline__ float gelu_tanh(float v) {
    float inner = 0.7978845608f * (v + 0.044715f * v * v * v);
    return 0.5f * v * (1.0f + tanhf(inner));
}

// ---------------------------------------------------------------------------
// Main kernel: CTA computes a (64-token x 64-M-row) output tile for row-block
// r = blockIdx.y. Scans all blocks, accumulates those with block_rows[n]==r.
// 256 threads = 16x16; each thread owns a 4(t) x 4(m) register microtile.
// ---------------------------------------------------------------------------
__global__ void __launch_bounds__(256) fused_sparse_linear_kernel(
    const float* __restrict__ x,
    const float* __restrict__ bias,
    const int*   __restrict__ brows,
    const int*   __restrict__ bcols,
    float*       __restrict__ out,
    int n_blocks)
{
    __shared__ float Xs[64 * 65];   // [t][k], pitch 65 (bank-spread scalar reads)
    __shared__ float Vs[64 * 64];   // [k][m], pitch 64 (float4-aligned reads)
    __shared__ int   s_rows[NBLK];
    __shared__ int   s_cols[NBLK];

    const int r  = blockIdx.y;
    const int t0 = blockIdx.x * BT;
    const int tx = threadIdx.x & 15;   // m quad
    const int ty = threadIdx.x >> 4;   // t quad

    for (int i = threadIdx.x; i < n_blocks; i += 256) {
        s_rows[i] = brows[i];
        s_cols[i] = bcols[i];
    }
    __syncthreads();

    float acc[4][4] = {};

    const int lt = threadIdx.x >> 4;   // 0..15 (row within load phase)
    const int kq = threadIdx.x & 15;   // 0..15 (float4 column within load phase)

    for (int n = 0; n < n_blocks; n++) {
        if (s_rows[n] != r) continue;
        const int c = s_cols[n];

        // Load X tile: 64 tokens x 64 k, coalesced float4 global reads,
        // scalar smem stores (2-way conflict max).
        const float4* xg = (const float4*)(x + (size_t)t0 * KDIM + (size_t)c * 64);
        #pragma unroll
        for (int it = 0; it < 4; it++) {
            int t = lt + it * 16;
            float4 v = xg[(size_t)t * (KDIM / 4) + kq];
            float* d = &Xs[t * 65 + kq * 4];
            d[0] = v.x; d[1] = v.y; d[2] = v.z; d[3] = v.w;
        }
        // Load V tile (pre-transposed [k][m]): fully coalesced, conflict-free.
        const float4* vg = (const float4*)(g_vT + (size_t)n * 4096);
        #pragma unroll
        for (int it = 0; it < 4; it++) {
            int k = lt + it * 16;
            *(float4*)&Vs[k * 64 + kq * 4] = vg[k * 16 + kq];
        }
        __syncthreads();

        // 64 k-steps: per step 1 LDS.128 (Vs) + 4 broadcast LDS.32 (Xs) -> 16 FFMA
        #pragma unroll 16
        for (int k = 0; k < 64; k++) {
            float4 b4 = *(const float4*)&Vs[k * 64 + tx * 4];
            float a0 = Xs[(ty * 4 + 0) * 65 + k];
            float a1 = Xs[(ty * 4 + 1) * 65 + k];
            float a2 = Xs[(ty * 4 + 2) * 65 + k];
            float a3 = Xs[(ty * 4 + 3) * 65 + k];
            acc[0][0] += a0 * b4.x; acc[0][1] += a0 * b4.y;
            acc[0][2] += a0 * b4.z; acc[0][3] += a0 * b4.w;
            acc[1][0] += a1 * b4.x; acc[1][1] += a1 * b4.y;
            acc[1][2] += a1 * b4.z; acc[1][3] += a1 * b4.w;
            acc[2][0] += a2 * b4.x; acc[2][1] += a2 * b4.y;
            acc[2][2] += a2 * b4.z; acc[2][3] += a2 * b4.w;
            acc[3][0] += a3 * b4.x; acc[3][1] += a3 * b4.y;
            acc[3][2] += a3 * b4.z; acc[3][3] += a3 * b4.w;
        }
        __syncthreads();
    }

    // Epilogue: bias + tanh-GELU, float4 stores.
    const int m0 = r * BM + tx * 4;
    const float4 bv = *(const float4*)&bias[m0];
    #pragma unroll
    for (int i = 0; i < 4; i++) {
        const int t = t0 + ty * 4 + i;
        float4 o;
        o.x = gelu_tanh(acc[i][0] + bv.x);
        o.y = gelu_tanh(acc[i][1] + bv.y);
        o.z = gelu_tanh(acc[i][2] + bv.z);
        o.w = gelu_tanh(acc[i][3] + bv.w);
        *(float4*)&out[(size_t)t * MDIM + m0] = o;
    }
}

extern "C" void kernel_launch(void* const* d_in, const int* in_sizes, int n_in,
                              void* d_out, int out_size)
{
    const float* x      = (const float*)d_in[0];
    const float* values = (const float*)d_in[1];
    const float* bias   = (const float*)d_in[2];
    const int*   brows  = (const int*)d_in[3];
    const int*   bcols  = (const int*)d_in[4];
    float*       out    = (float*)d_out;

    const int n_blocks = in_sizes[3];            // 1024
    const int T        = in_sizes[0] / KDIM;     // 2048

    transpose_values_kernel<<<n_blocks, 256>>>(values, n_blocks);

    dim3 grid(T / BT, MDIM / BM);                // (32, 64)
    fused_sparse_linear_kernel<<<grid, 256>>>(x, bias, brows, bcols, out, n_blocks);
}

// round 4
// speedup vs baseline: 3.2978x; 3.2978x over previous
#include <cuda_runtime.h>
#include <cuda_bf16.h>
#include <cstdint>

// Shapes (fixed): x (2048,4096) fp32, values (1024,64,64) fp32, bias (4096,),
// block_rows/cols (1024,) int32 in [0,64), out (2048,4096) fp32.
#define KDIM  4096
#define MDIM  4096
#define TTOK  2048
#define NBMAX 1024
#define MT    128            // tokens per CTA
#define NT    64             // out features per CTA (one row block)

// Smem tile pitch: 72 bf16 = 144B per row (odd multiple of 16B -> conflict-free LDSM)
#define PITCH   72
#define XBYTES  (128 * PITCH * 2)   // 18432
#define VBYTES  (64  * PITCH * 2)   // 9216
#define STAGE   (2 * XBYTES + 2 * VBYTES)  // 55296
#define SMEM_TOTAL (2 * STAGE)             // 110592

// ---- device scratch (static globals; no allocations allowed) ----
__device__ __nv_bfloat16 g_xhi[TTOK * KDIM];
__device__ __nv_bfloat16 g_xlo[TTOK * KDIM];
__device__ __nv_bfloat16 g_vhi[NBMAX * 64 * 64];
__device__ __nv_bfloat16 g_vlo[NBMAX * 64 * 64];
__device__ int g_row_list[64 * NBMAX];
__device__ int g_row_cnt[64];

// ---- PTX helpers (all baseline sm_80+ features; no 'a'-gated instructions) ----
__device__ __forceinline__ uint32_t smem_u32(const void* p) {
    uint32_t a;
    asm("{ .reg .u64 t; cvta.to.shared.u64 t, %1; cvt.u32.u64 %0, t; }" : "=r"(a) : "l"(p));
    return a;
}
__device__ __forceinline__ void cp_async16(uint32_t saddr, const void* gaddr) {
    asm volatile("cp.async.cg.shared.global [%0], [%1], 16;" :: "r"(saddr), "l"(gaddr));
}
#define CP_COMMIT() asm volatile("cp.async.commit_group;" ::: "memory")
#define CP_WAIT(n)  asm volatile("cp.async.wait_group %0;" :: "n"(n) : "memory")

__device__ __forceinline__ void ldsm_x4(uint32_t* r, uint32_t addr) {
    asm volatile("ldmatrix.sync.aligned.m8n8.x4.shared.b16 {%0,%1,%2,%3}, [%4];"
                 : "=r"(r[0]), "=r"(r[1]), "=r"(r[2]), "=r"(r[3]) : "r"(addr));
}
__device__ __forceinline__ void mma_bf16(float* d, const uint32_t* a, uint32_t b0, uint32_t b1) {
    asm volatile(
        "mma.sync.aligned.m16n8k16.row.col.f32.bf16.bf16.f32 "
        "{%0,%1,%2,%3}, {%4,%5,%6,%7}, {%8,%9}, {%0,%1,%2,%3};"
        : "+f"(d[0]), "+f"(d[1]), "+f"(d[2]), "+f"(d[3])
        : "r"(a[0]), "r"(a[1]), "r"(a[2]), "r"(a[3]), "r"(b0), "r"(b1));
}

__device__ __forceinline__ float gelu_tanh(float v) {
    float inner = 0.7978845608f * (v + 0.044715f * v * v * v);
    return 0.5f * v * (1.0f + tanhf(inner));
}

// ---------------------------------------------------------------------------
// Pre-pass 1: fp32 -> bf16 hi/lo split (which=0 -> x, 1 -> values)
// ---------------------------------------------------------------------------
__global__ void __launch_bounds__(256) convert_split_kernel(
    const float* __restrict__ src, int n4, int which)
{
    uint2* h2 = (uint2*)(which ? g_vhi : g_xhi);
    uint2* l2 = (uint2*)(which ? g_vlo : g_xlo);
    const float4* s4 = (const float4*)src;
    int stride = gridDim.x * blockDim.x;
    for (int i = blockIdx.x * blockDim.x + threadIdx.x; i < n4; i += stride) {
        float4 v = s4[i];
        __nv_bfloat16 hx = __float2bfloat16_rn(v.x);
        __nv_bfloat16 hy = __float2bfloat16_rn(v.y);
        __nv_bfloat16 hz = __float2bfloat16_rn(v.z);
        __nv_bfloat16 hw = __float2bfloat16_rn(v.w);
        __nv_bfloat16 lx = __float2bfloat16_rn(v.x - __bfloat162float(hx));
        __nv_bfloat16 ly = __float2bfloat16_rn(v.y - __bfloat162float(hy));
        __nv_bfloat16 lz = __float2bfloat16_rn(v.z - __bfloat162float(hz));
        __nv_bfloat16 lw = __float2bfloat16_rn(v.w - __bfloat162float(hw));
        __nv_bfloat162 p0{hx, hy}, p1{hz, hw}, q0{lx, ly}, q1{lz, lw};
        uint2 H{*(uint32_t*)&p0, *(uint32_t*)&p1};
        uint2 L{*(uint32_t*)&q0, *(uint32_t*)&q1};
        h2[i] = H;
        l2[i] = L;
    }
}

// ---------------------------------------------------------------------------
// Pre-pass 2: per-row compacted block lists (stable order -> deterministic)
// ---------------------------------------------------------------------------
__global__ void __launch_bounds__(32) build_lists_kernel(
    const int* __restrict__ brows, int nb)
{
    int r = blockIdx.x, lane = threadIdx.x, cnt = 0;
    for (int base = 0; base < nb; base += 32) {
        int n = base + lane;
        int row = (n < nb) ? brows[n] : -1;
        unsigned m = __ballot_sync(0xFFFFFFFFu, row == r);
        if (row == r)
            g_row_list[r * NBMAX + cnt + __popc(m & ((1u << lane) - 1u))] = n;
        cnt += __popc(m);
    }
    if (lane == 0) g_row_cnt[r] = cnt;
}

// ---------------------------------------------------------------------------
// Stage loader: cp.async X (hi/lo, 128x64) and V (hi/lo, 64x64) into stage s.
// ---------------------------------------------------------------------------
__device__ __forceinline__ void load_stage(uint32_t sb, int s, int n, int c,
                                           int t0, int tid)
{
    const uint32_t xh = sb + s * STAGE;
    const uint32_t xl = xh + XBYTES;
    const uint32_t vh = xl + XBYTES;
    const uint32_t vl = vh + VBYTES;
    // X: 1024 16B chunks (128 rows x 8 chunks)
    #pragma unroll
    for (int i = 0; i < 4; i++) {
        const int id = tid + i * 256;
        const int row = id >> 3, cb = id & 7;
        const size_t g = (size_t)(t0 + row) * KDIM + (size_t)c * 64 + cb * 8;
        const uint32_t so = row * (PITCH * 2) + cb * 16;
        cp_async16(xh + so, g_xhi + g);
        cp_async16(xl + so, g_xlo + g);
    }
    // V: 512 16B chunks (64 rows x 8 chunks)
    #pragma unroll
    for (int i = 0; i < 2; i++) {
        const int id = tid + i * 256;
        const int row = id >> 3, cb = id & 7;
        const size_t g = (size_t)n * 4096 + row * 64 + cb * 8;
        const uint32_t so = row * (PITCH * 2) + cb * 16;
        cp_async16(vh + so, g_vhi + g);
        cp_async16(vl + so, g_vlo + g);
    }
}

// ---------------------------------------------------------------------------
// Main kernel: 256 threads = 8 warps (4 token-groups x 2 n-groups),
// warp tile 32(t) x 32(n), bf16 HMMA with 3-product split, fp32 accum.
// ---------------------------------------------------------------------------
__global__ void __launch_bounds__(256, 2) fsl_hmma_kernel(
    const float* __restrict__ bias,
    const int*   __restrict__ bcols,
    float*       __restrict__ out)
{
    extern __shared__ char smem[];
    const uint32_t sb = smem_u32(smem);
    const int tid  = threadIdx.x;
    const int warp = tid >> 5;
    const int lane = tid & 31;
    const int r  = blockIdx.y;
    const int t0 = blockIdx.x * MT;

    const int wt = (warp >> 1) * 32;   // warp token offset in tile
    const int wn = (warp & 1) * 32;    // warp n offset in tile

    const int cnt = g_row_cnt[r];
    const int* list = &g_row_list[r * NBMAX];

    float acc[2][4][4];
    #pragma unroll
    for (int mi = 0; mi < 2; mi++)
        #pragma unroll
        for (int nj = 0; nj < 4; nj++)
            #pragma unroll
            for (int q = 0; q < 4; q++) acc[mi][nj][q] = 0.0f;

    // ldmatrix lane-address components (fixed per thread)
    const int a_m = (lane & 7) + ((lane >> 3) & 1) * 8;   // + wt + mi*16
    const int a_k = (lane >> 4) * 8;                      // + kc*16
    const int b_n = (lane & 7) + ((lane >> 4) & 1) * 8;   // + wn + j*16
    const int b_k = ((lane >> 3) & 1) * 8;                // + kc*16

    // Prologue: prime both stages
    if (cnt > 0) { load_stage(sb, 0, list[0], __ldg(&bcols[list[0]]), t0, tid); }
    CP_COMMIT();
    if (cnt > 1) { load_stage(sb, 1, list[1], __ldg(&bcols[list[1]]), t0, tid); }
    CP_COMMIT();

    for (int idx = 0; idx < cnt; idx++) {
        if (idx + 1 < cnt) CP_WAIT(1); else CP_WAIT(0);
        __syncthreads();

        const int s = idx & 1;
        const uint32_t xh = sb + s * STAGE;
        const uint32_t xl = xh + XBYTES;
        const uint32_t vh = xl + XBYTES;
        const uint32_t vl = vh + VBYTES;

        #pragma unroll
        for (int kc = 0; kc < 4; kc++) {
            uint32_t ah[2][4], al[2][4], bh[2][4], bl[2][4];
            const uint32_t ao = (wt + a_m) * (PITCH * 2) + (kc * 16 + a_k) * 2;
            const uint32_t bo = (wn + b_n) * (PITCH * 2) + (kc * 16 + b_k) * 2;
            #pragma unroll
            for (int mi = 0; mi < 2; mi++) {
                ldsm_x4(ah[mi], xh + ao + mi * 16 * (PITCH * 2));
                ldsm_x4(al[mi], xl + ao + mi * 16 * (PITCH * 2));
            }
            #pragma unroll
            for (int j = 0; j < 2; j++) {
                ldsm_x4(bh[j], vh + bo + j * 16 * (PITCH * 2));
                ldsm_x4(bl[j], vl + bo + j * 16 * (PITCH * 2));
            }
            #pragma unroll
            for (int mi = 0; mi < 2; mi++) {
                #pragma unroll
                for (int j = 0; j < 2; j++) {
                    // hi*hi
                    mma_bf16(acc[mi][2 * j + 0], ah[mi], bh[j][0], bh[j][1]);
                    mma_bf16(acc[mi][2 * j + 1], ah[mi], bh[j][2], bh[j][3]);
                    // hi*lo
                    mma_bf16(acc[mi][2 * j + 0], ah[mi], bl[j][0], bl[j][1]);
                    mma_bf16(acc[mi][2 * j + 1], ah[mi], bl[j][2], bl[j][3]);
                    // lo*hi
                    mma_bf16(acc[mi][2 * j + 0], al[mi], bh[j][0], bh[j][1]);
                    mma_bf16(acc[mi][2 * j + 1], al[mi], bh[j][2], bh[j][3]);
                }
            }
        }
        __syncthreads();
        if (idx + 2 < cnt) {
            load_stage(sb, s, list[idx + 2], __ldg(&bcols[list[idx + 2]]), t0, tid);
        }
        CP_COMMIT();   // keep group count uniform across iterations/threads
    }

    // Epilogue: bias + tanh-GELU, float2 stores.
    const int row0 = lane >> 2;           // 0..7
    const int cp2  = (lane & 3) * 2;      // 0,2,4,6
    #pragma unroll
    for (int mi = 0; mi < 2; mi++) {
        #pragma unroll
        for (int nj = 0; nj < 4; nj++) {
            const int nb = wn + nj * 8 + cp2;
            const float b0 = __ldg(&bias[r * 64 + nb]);
            const float b1 = __ldg(&bias[r * 64 + nb + 1]);
            #pragma unroll
            for (int h = 0; h < 2; h++) {   // regs {0,1} -> row0, {2,3} -> row0+8
                const int m = wt + mi * 16 + row0 + h * 8;
                float2 o;
                o.x = gelu_tanh(acc[mi][nj][2 * h + 0] + b0);
                o.y = gelu_tanh(acc[mi][nj][2 * h + 1] + b1);
                *(float2*)&out[(size_t)(t0 + m) * MDIM + r * 64 + nb] = o;
            }
        }
    }
}

// ---------------------------------------------------------------------------
extern "C" void kernel_launch(void* const* d_in, const int* in_sizes, int n_in,
                              void* d_out, int out_size)
{
    const float* x      = (const float*)d_in[0];
    const float* values = (const float*)d_in[1];
    const float* bias   = (const float*)d_in[2];
    const int*   brows  = (const int*)d_in[3];
    const int*   bcols  = (const int*)d_in[4];
    float*       out    = (float*)d_out;

    const int n_blocks = in_sizes[3];
    const int x_elems  = in_sizes[0];
    const int v_elems  = in_sizes[1];

    cudaFuncSetAttribute(fsl_hmma_kernel,
                         cudaFuncAttributeMaxDynamicSharedMemorySize, SMEM_TOTAL);

    convert_split_kernel<<<2048, 256>>>(x, x_elems / 4, 0);
    convert_split_kernel<<<1024, 256>>>(values, v_elems / 4, 1);
    build_lists_kernel<<<64, 32>>>(brows, n_blocks);

    dim3 grid(TTOK / MT, MDIM / NT);   // (16, 64)
    fsl_hmma_kernel<<<grid, 256, SMEM_TOTAL>>>(bias, bcols, out);
}